// round 13
// baseline (speedup 1.0000x reference)
#include <cuda_runtime.h>
#include <cuda_bf16.h>
#include <math.h>

#define B_SZ 8
#define N_SZ 2048
#define F_SZ 128
#define ROWS_TOTAL (B_SZ * N_SZ)
#define ALPHA 0.2f
#define LN_EPS 1e-5f

// Scratch (__device__ globals: allocation-free rule)
__device__ float          g_h [ROWS_TOTAL * F_SZ];   // post-LN h fp32 (residual)
__device__ __nv_bfloat16  g_hb[ROWS_TOTAL * F_SZ];   // post-LN h bf16 (mma B operand)
__device__ float4         g_rc[ROWS_TOTAL];          // {exp(s1), exp(a*s1), -, -}
__device__ float2         g_e2[ROWS_TOTAL];          // {exp(s2), exp(a*s2)}
__device__ unsigned       g_adjbits[N_SZ * (N_SZ / 32)];

// ---------------------------------------------------------------------------
// Kernel 1: blocks [0,256): prep, 64 rows/block (W traffic halved vs 32-row).
//           blocks [256,384): pack adj -> bitmask, 128 ints -> 4 words/thread.
// ---------------------------------------------------------------------------
__global__ void __launch_bounds__(256) prep_kernel(
    const float* __restrict__ x, const int* __restrict__ adj,
    const float* __restrict__ W, const float* __restrict__ a,
    const float* __restrict__ nw, const float* __restrict__ nb,
    const float* __restrict__ gamma, const float* __restrict__ beta)
{
    const int tid = threadIdx.x;
    if (blockIdx.x >= 256) {                               // ---- pack ----
        const int wbase = (blockIdx.x - 256) * 1024;       // block covers 1024 words
#pragma unroll
        for (int ww = 0; ww < 4; ww++) {
            int word = wbase + ww * 256 + tid;
            const int4* src = (const int4*)adj + (size_t)word * 8;
            unsigned bits = 0;
#pragma unroll
            for (int u = 0; u < 8; u++) {
                int4 v = src[u];
                bits |= (v.x > 0 ? 1u : 0u) << (4 * u);
                bits |= (v.y > 0 ? 1u : 0u) << (4 * u + 1);
                bits |= (v.z > 0 ? 1u : 0u) << (4 * u + 2);
                bits |= (v.w > 0 ? 1u : 0u) << (4 * u + 3);
            }
            g_adjbits[word] = bits;
        }
        return;
    }

    extern __shared__ float sm[];
    float* Ws  = sm;               // 16384
    float* xs  = sm + 16384;       // 64*128 = 8192
    float* a1s = xs + 8192;        // 128
    float* a2s = a1s + 128;        // 128
    float* gs  = a2s + 128;        // 128
    float* bs  = gs + 128;         // 128

    const int row0 = blockIdx.x * 64;

#pragma unroll
    for (int k = 0; k < 64; k++) Ws[k * 256 + tid] = W[k * 256 + tid];
#pragma unroll
    for (int k = 0; k < 32; k++) {
        int idx = k * 256 + tid;
        int rl = idx >> 7, f = idx & 127;
        int row = row0 + rl;
        int n = row & (N_SZ - 1);
        xs[idx] = x[(size_t)row * F_SZ + f] * (1.0f + nw[n]) + nb[n];
    }
    if (tid < 128) {
        a1s[tid] = a[tid];
        a2s[tid] = a[128 + tid];
        gs[tid]  = gamma[tid];
        bs[tid]  = beta[tid];
    }
    __syncthreads();

    const int w = tid >> 5, lane = tid & 31;
    const int rbase = w * 8;
    float acc[8][4];
#pragma unroll
    for (int r = 0; r < 8; r++)
#pragma unroll
        for (int k = 0; k < 4; k++) acc[r][k] = 0.0f;

#pragma unroll 2
    for (int f = 0; f < 128; f++) {
        float w0 = Ws[f * 128 + lane];
        float w1 = Ws[f * 128 + 32 + lane];
        float w2 = Ws[f * 128 + 64 + lane];
        float w3 = Ws[f * 128 + 96 + lane];
#pragma unroll
        for (int r = 0; r < 8; r++) {
            float xv = xs[(rbase + r) * 128 + f];
            acc[r][0] += xv * w0;
            acc[r][1] += xv * w1;
            acc[r][2] += xv * w2;
            acc[r][3] += xv * w3;
        }
    }

#pragma unroll
    for (int r = 0; r < 8; r++) {
        int row = row0 + rbase + r;
        float s = acc[r][0] + acc[r][1] + acc[r][2] + acc[r][3];
#pragma unroll
        for (int o = 16; o; o >>= 1) s += __shfl_xor_sync(0xffffffffu, s, o);
        float mu = s * 0.0078125f;
        float d0 = acc[r][0] - mu, d1 = acc[r][1] - mu;
        float d2 = acc[r][2] - mu, d3 = acc[r][3] - mu;
        float v = d0 * d0 + d1 * d1 + d2 * d2 + d3 * d3;
#pragma unroll
        for (int o = 16; o; o >>= 1) v += __shfl_xor_sync(0xffffffffu, v, o);
        float rstd = rsqrtf(v * 0.0078125f + LN_EPS);
        float h0 = d0 * rstd * gs[lane]      + bs[lane];
        float h1 = d1 * rstd * gs[32 + lane] + bs[32 + lane];
        float h2 = d2 * rstd * gs[64 + lane] + bs[64 + lane];
        float h3 = d3 * rstd * gs[96 + lane] + bs[96 + lane];
        float s1p = h0 * a1s[lane] + h1 * a1s[32 + lane] + h2 * a1s[64 + lane] + h3 * a1s[96 + lane];
        float s2p = h0 * a2s[lane] + h1 * a2s[32 + lane] + h2 * a2s[64 + lane] + h3 * a2s[96 + lane];
#pragma unroll
        for (int o = 16; o; o >>= 1) {
            s1p += __shfl_xor_sync(0xffffffffu, s1p, o);
            s2p += __shfl_xor_sync(0xffffffffu, s2p, o);
        }
        size_t ro = (size_t)row * F_SZ;
        g_h[ro + lane]      = h0;
        g_h[ro + 32 + lane] = h1;
        g_h[ro + 64 + lane] = h2;
        g_h[ro + 96 + lane] = h3;
        g_hb[ro + lane]      = __float2bfloat16(h0);
        g_hb[ro + 32 + lane] = __float2bfloat16(h1);
        g_hb[ro + 64 + lane] = __float2bfloat16(h2);
        g_hb[ro + 96 + lane] = __float2bfloat16(h3);
        if (lane == 0) {
            g_rc[row] = make_float4(__expf(s1p), __expf(ALPHA * s1p), 0.0f, 0.0f);
            g_e2[row] = make_float2(__expf(s2p), __expf(ALPHA * s2p));
        }
    }
}

// ---------------------------------------------------------------------------
// Kernel 2: attention (unchanged from R12 — at the legacy-HMMA rate ceiling).
// 1024 threads, 128x128 tile. mma: warp w: cc=w&7 -> rows cc*16, dd=w>>3 ->
// f-cols dd*32. pass-1: warp w owns rows {w,w+32,w+64,w+96}; lane owns
// j=4*lane..+3; p = mask ? max(E1*E2, F1*F2) : 0 (exp-free), via __ldg.
// One __syncthreads per tile; stage(T+1)+pass1(T+1) overlap mma(T).
// ---------------------------------------------------------------------------
__global__ void __launch_bounds__(1024, 1) attn_kernel(float* __restrict__ out)
{
    extern __shared__ char smc[];
    const unsigned HS_BYTES = 128 * 272;             // 34816
    const unsigned PS_OFF   = 2 * HS_BYTES;          // 69632
    const unsigned LS_OFF   = PS_OFF + 2 * HS_BYTES; // 139264

    unsigned* Ps32 = (unsigned*)(smc + PS_OFF);
    float*    l_s  = (float*)(smc + LS_OFF);         // [128]

    const unsigned smemBase = (unsigned)__cvta_generic_to_shared(smc);
    const unsigned psBase   = smemBase + PS_OFF;

    const int tid  = threadIdx.x;
    const int w    = tid >> 5;          // 0..31
    const int lane = tid & 31;
    const int cc   = w & 7;             // mma i-group
    const int dd   = w >> 3;            // mma f-block
    const int b    = blockIdx.y;
    const int i0   = blockIdx.x * 128;
    const int bN   = b * N_SZ;

    const __nv_bfloat16* hbb = g_hb + (size_t)bN * F_SZ;
    const float*         hbf = g_h  + (size_t)bN * F_SZ;

    // ---- pass-1 identity: rows w+32m, j = 4*lane..+3 ----
    float E1[4], F1[4];
#pragma unroll
    for (int m = 0; m < 4; m++) {
        float4 rc = g_rc[bN + i0 + w + 32 * m];
        E1[m] = rc.x; F1[m] = rc.y;
    }
    const unsigned* mbase0 = g_adjbits + (size_t)(i0 + w) * 64 + (lane >> 3);
    const float2*   e2b    = g_e2 + bN + 4 * lane;     // + T*128 (+2 for 2nd float4)
    const unsigned  sh0    = 4u * (unsigned)(lane & 7);

    // ---- mma ldmatrix addresses ----
    const unsigned aOff  = psBase + (unsigned)(cc * 16 + (lane & 15)) * 272
                         + (unsigned)(lane >> 4) * 16;
    const unsigned bRow  = (unsigned)(lane & 15) * 272;
    const unsigned bCol0 = (unsigned)(dd * 32 + (lane >> 4) * 8) * 2;
    const unsigned bCol1 = bCol0 + 32;

    float acc[4][4];
#pragma unroll
    for (int n = 0; n < 4; n++)
#pragma unroll
        for (int r = 0; r < 4; r++) acc[n][r] = 0.0f;
    float lacc[4] = {0.f, 0.f, 0.f, 0.f};

    // ---- staging: tile T (128x128 bf16 = 32KB) via 2 cp.async per thread ----
    auto stage = [&](int T, int buf) {
        unsigned dbase = smemBase + (unsigned)buf * HS_BYTES;
#pragma unroll
        for (int kk = 0; kk < 2; kk++) {
            int idx = kk * 1024 + tid;
            int row = idx >> 4, c16 = idx & 15;
            unsigned dst = dbase + (unsigned)row * 272 + (unsigned)c16 * 16;
            const void* src = hbb + (size_t)(T * 128 + row) * F_SZ + c16 * 8;
            asm volatile("cp.async.cg.shared.global [%0], [%1], 16;" :: "r"(dst), "l"(src));
        }
        asm volatile("cp.async.commit_group;");
    };

    // ---- pass 1 for tile T into Ps[buf] ----
    auto pass1 = [&](int T, int buf) {
        unsigned mw[4];
#pragma unroll
        for (int m = 0; m < 4; m++) mw[m] = __ldg(mbase0 + m * 32 * 64 + 4 * T);
        float4 ef0 = __ldg((const float4*)(e2b + T * 128));       // j=4l, 4l+1
        float4 ef1 = __ldg((const float4*)(e2b + T * 128 + 2));   // j=4l+2, 4l+3
        unsigned* psb = Ps32 + buf * 8704 + 2 * lane;
#pragma unroll
        for (int m = 0; m < 4; m++) {
            unsigned bits = (mw[m] >> sh0) & 0xFu;
            float pa0 = fmaxf(E1[m] * ef0.x, F1[m] * ef0.y);
            float pb0 = fmaxf(E1[m] * ef0.z, F1[m] * ef0.w);
            float pa1 = fmaxf(E1[m] * ef1.x, F1[m] * ef1.y);
            float pb1 = fmaxf(E1[m] * ef1.z, F1[m] * ef1.w);
            pa0 = (bits & 1u) ? pa0 : 0.0f;
            pb0 = (bits & 2u) ? pb0 : 0.0f;
            pa1 = (bits & 4u) ? pa1 : 0.0f;
            pb1 = (bits & 8u) ? pb1 : 0.0f;
            __nv_bfloat162 q0 = __floats2bfloat162_rn(pa0, pb0);
            __nv_bfloat162 q1 = __floats2bfloat162_rn(pa1, pb1);
            uint2 qq = make_uint2(*(unsigned*)&q0, *(unsigned*)&q1);
            *(uint2*)(psb + (w + 32 * m) * 68) = qq;
            lacc[m] += (pa0 + pb0) + (pa1 + pb1);
        }
    };

    // ---- prologue: tile 0 ----
    stage(0, 0);
    pass1(0, 0);
    asm volatile("cp.async.wait_group 0;");

    for (int T = 0; T < 16; T++) {
        const int buf = T & 1;
        __syncthreads();   // Ps[buf], Hs[buf] (tile T) visible to all warps

        if (T < 15) {
            stage(T + 1, buf ^ 1);
            pass1(T + 1, buf ^ 1);
        }

        // ---- mma(T): ACC += P[cc-group] @ H[:, dd-slab] ----
        const unsigned hsB = smemBase + (unsigned)buf * HS_BYTES;
        const unsigned psB = (unsigned)buf * HS_BYTES;
#pragma unroll
        for (int k = 0; k < 8; k++) {
            unsigned af[4];
            {
                unsigned addr = aOff + psB + (unsigned)k * 32;
                asm volatile("ldmatrix.sync.aligned.m8n8.x4.shared.b16 {%0,%1,%2,%3}, [%4];"
                             : "=r"(af[0]), "=r"(af[1]), "=r"(af[2]), "=r"(af[3])
                             : "r"(addr));
            }
            unsigned bb[2][4];
            {
                unsigned addr = hsB + bRow + (unsigned)k * 16 * 272 + bCol0;
                asm volatile("ldmatrix.sync.aligned.m8n8.x4.trans.shared.b16 {%0,%1,%2,%3}, [%4];"
                             : "=r"(bb[0][0]), "=r"(bb[0][1]), "=r"(bb[0][2]), "=r"(bb[0][3])
                             : "r"(addr));
                addr = hsB + bRow + (unsigned)k * 16 * 272 + bCol1;
                asm volatile("ldmatrix.sync.aligned.m8n8.x4.trans.shared.b16 {%0,%1,%2,%3}, [%4];"
                             : "=r"(bb[1][0]), "=r"(bb[1][1]), "=r"(bb[1][2]), "=r"(bb[1][3])
                             : "r"(addr));
            }
#pragma unroll
            for (int n = 0; n < 4; n++) {
                asm volatile(
                    "mma.sync.aligned.m16n8k16.row.col.f32.bf16.bf16.f32 "
                    "{%0,%1,%2,%3}, {%4,%5,%6,%7}, {%8,%9}, {%0,%1,%2,%3};"
                    : "+f"(acc[n][0]), "+f"(acc[n][1]),
                      "+f"(acc[n][2]), "+f"(acc[n][3])
                    : "r"(af[0]), "r"(af[1]), "r"(af[2]), "r"(af[3]),
                      "r"(bb[n >> 1][2 * (n & 1)]), "r"(bb[n >> 1][2 * (n & 1) + 1]));
            }
        }

        asm volatile("cp.async.wait_group 0;");   // own stage(T+1) copies landed
    }

    // ---- l: full warp reduce (each row owned by exactly one warp) ----
#pragma unroll
    for (int m = 0; m < 4; m++) {
#pragma unroll
        for (int o = 16; o; o >>= 1) lacc[m] += __shfl_xor_sync(0xffffffffu, lacc[m], o);
        if (lane == 0) l_s[w + 32 * m] = lacc[m];
    }
    __syncthreads();

    // ---- epilogue: normalize, +residual, elu ----
#pragma unroll
    for (int rp = 0; rp < 2; rp++) {
        int rl = cc * 16 + (lane >> 2) + 8 * rp;
        float invl = 1.0f / l_s[rl];
        int i = i0 + rl;
#pragma unroll
        for (int n = 0; n < 4; n++) {
            int col = dd * 32 + n * 8 + (lane & 3) * 2;
            const float2 r = *(const float2*)(hbf + (size_t)i * F_SZ + col);
            float ox = acc[n][2 * rp]     * invl + r.x;
            float oy = acc[n][2 * rp + 1] * invl + r.y;
            ox = ox > 0.0f ? ox : __expf(ox) - 1.0f;
            oy = oy > 0.0f ? oy : __expf(oy) - 1.0f;
            *(float2*)(out + ((size_t)bN + i) * F_SZ + col) = make_float2(ox, oy);
        }
    }
}

// ---------------------------------------------------------------------------
extern "C" void kernel_launch(void* const* d_in, const int* in_sizes, int n_in,
                              void* d_out, int out_size)
{
    const float* x     = (const float*)d_in[0];
    const int*   adj   = (const int*)d_in[1];
    const float* W     = (const float*)d_in[2];
    const float* a     = (const float*)d_in[3];
    const float* nw    = (const float*)d_in[4];
    const float* nb    = (const float*)d_in[5];
    const float* gamma = (const float*)d_in[6];
    const float* beta  = (const float*)d_in[7];
    float* out = (float*)d_out;

    const int prep_smem = (16384 + 8192 + 4 * 128) * 4;       // 100352 B
    const int attn_smem = 139264 + 512;                        // 139776 B
    cudaFuncSetAttribute(prep_kernel, cudaFuncAttributeMaxDynamicSharedMemorySize, prep_smem);
    cudaFuncSetAttribute(attn_kernel, cudaFuncAttributeMaxDynamicSharedMemorySize, attn_smem);

    prep_kernel<<<384, 256, prep_smem>>>(x, adj, W, a, nw, nb, gamma, beta);

    dim3 grid(N_SZ / 128, B_SZ);
    attn_kernel<<<grid, 1024, attn_smem>>>(out);
}

// round 14
// speedup vs baseline: 1.0979x; 1.0979x over previous
#include <cuda_runtime.h>
#include <cuda_bf16.h>
#include <math.h>

#define B_SZ 8
#define N_SZ 2048
#define F_SZ 128
#define ROWS_TOTAL (B_SZ * N_SZ)
#define ALPHA 0.2f
#define LN_EPS 1e-5f

// Scratch (__device__ globals: allocation-free rule)
__device__ float          g_h [ROWS_TOTAL * F_SZ];   // post-LN h fp32 (residual)
__device__ __nv_bfloat16  g_hb[ROWS_TOTAL * F_SZ];   // post-LN h bf16 (mma B operand)
__device__ float4         g_rc[ROWS_TOTAL];          // {exp(s1), exp(a*s1), -, -}
__device__ float2         g_e2[ROWS_TOTAL];          // {exp(s2), exp(a*s2)}
__device__ unsigned       g_adjbits[N_SZ * (N_SZ / 32)];

// ---------------------------------------------------------------------------
// Kernel 1: blocks [0,512): prep, 32 rows/block (R12 shape — best measured).
//           blocks [512,1024): pack adj -> bitmask; 8 int4 loads batched into
//           an explicit array FIRST (MLP=8) so the branch is DRAM-bound, not
//           latency-bound.
// ---------------------------------------------------------------------------
__global__ void __launch_bounds__(256) prep_kernel(
    const float* __restrict__ x, const int* __restrict__ adj,
    const float* __restrict__ W, const float* __restrict__ a,
    const float* __restrict__ nw, const float* __restrict__ nb,
    const float* __restrict__ gamma, const float* __restrict__ beta)
{
    const int tid = threadIdx.x;
    if (blockIdx.x >= 512) {                               // ---- pack ----
        int gid = (blockIdx.x - 512) * 256 + tid;
        const int4* src = (const int4*)adj + (size_t)gid * 8;
        int4 v[8];
#pragma unroll
        for (int u = 0; u < 8; u++) v[u] = src[u];          // 8 independent LDG.128
        unsigned bits = 0;
#pragma unroll
        for (int u = 0; u < 8; u++) {
            bits |= (v[u].x > 0 ? 1u : 0u) << (4 * u);
            bits |= (v[u].y > 0 ? 1u : 0u) << (4 * u + 1);
            bits |= (v[u].z > 0 ? 1u : 0u) << (4 * u + 2);
            bits |= (v[u].w > 0 ? 1u : 0u) << (4 * u + 3);
        }
        g_adjbits[gid] = bits;
        return;
    }

    extern __shared__ float sm[];
    float* Ws  = sm;               // 16384
    float* xs  = sm + 16384;       // 4096
    float* a1s = xs + 4096;        // 128
    float* a2s = a1s + 128;        // 128
    float* gs  = a2s + 128;        // 128
    float* bs  = gs + 128;         // 128

    const int row0 = blockIdx.x * 32;

#pragma unroll
    for (int k = 0; k < 64; k++) Ws[k * 256 + tid] = W[k * 256 + tid];
#pragma unroll
    for (int k = 0; k < 16; k++) {
        int idx = k * 256 + tid;
        int rl = idx >> 7, f = idx & 127;
        int row = row0 + rl;
        int n = row & (N_SZ - 1);
        xs[idx] = x[(size_t)row * F_SZ + f] * (1.0f + nw[n]) + nb[n];
    }
    if (tid < 128) {
        a1s[tid] = a[tid];
        a2s[tid] = a[128 + tid];
        gs[tid]  = gamma[tid];
        bs[tid]  = beta[tid];
    }
    __syncthreads();

    const int w = tid >> 5, lane = tid & 31;
    const int rbase = w * 4;
    float acc[4][4];
#pragma unroll
    for (int r = 0; r < 4; r++)
#pragma unroll
        for (int k = 0; k < 4; k++) acc[r][k] = 0.0f;

#pragma unroll 2
    for (int f = 0; f < 128; f++) {
        float w0 = Ws[f * 128 + lane];
        float w1 = Ws[f * 128 + 32 + lane];
        float w2 = Ws[f * 128 + 64 + lane];
        float w3 = Ws[f * 128 + 96 + lane];
#pragma unroll
        for (int r = 0; r < 4; r++) {
            float xv = xs[(rbase + r) * 128 + f];
            acc[r][0] += xv * w0;
            acc[r][1] += xv * w1;
            acc[r][2] += xv * w2;
            acc[r][3] += xv * w3;
        }
    }

#pragma unroll
    for (int r = 0; r < 4; r++) {
        int row = row0 + rbase + r;
        float s = acc[r][0] + acc[r][1] + acc[r][2] + acc[r][3];
#pragma unroll
        for (int o = 16; o; o >>= 1) s += __shfl_xor_sync(0xffffffffu, s, o);
        float mu = s * 0.0078125f;
        float d0 = acc[r][0] - mu, d1 = acc[r][1] - mu;
        float d2 = acc[r][2] - mu, d3 = acc[r][3] - mu;
        float v = d0 * d0 + d1 * d1 + d2 * d2 + d3 * d3;
#pragma unroll
        for (int o = 16; o; o >>= 1) v += __shfl_xor_sync(0xffffffffu, v, o);
        float rstd = rsqrtf(v * 0.0078125f + LN_EPS);
        float h0 = d0 * rstd * gs[lane]      + bs[lane];
        float h1 = d1 * rstd * gs[32 + lane] + bs[32 + lane];
        float h2 = d2 * rstd * gs[64 + lane] + bs[64 + lane];
        float h3 = d3 * rstd * gs[96 + lane] + bs[96 + lane];
        float s1p = h0 * a1s[lane] + h1 * a1s[32 + lane] + h2 * a1s[64 + lane] + h3 * a1s[96 + lane];
        float s2p = h0 * a2s[lane] + h1 * a2s[32 + lane] + h2 * a2s[64 + lane] + h3 * a2s[96 + lane];
#pragma unroll
        for (int o = 16; o; o >>= 1) {
            s1p += __shfl_xor_sync(0xffffffffu, s1p, o);
            s2p += __shfl_xor_sync(0xffffffffu, s2p, o);
        }
        size_t ro = (size_t)row * F_SZ;
        g_h[ro + lane]      = h0;
        g_h[ro + 32 + lane] = h1;
        g_h[ro + 64 + lane] = h2;
        g_h[ro + 96 + lane] = h3;
        g_hb[ro + lane]      = __float2bfloat16(h0);
        g_hb[ro + 32 + lane] = __float2bfloat16(h1);
        g_hb[ro + 64 + lane] = __float2bfloat16(h2);
        g_hb[ro + 96 + lane] = __float2bfloat16(h3);
        if (lane == 0) {
            g_rc[row] = make_float4(__expf(s1p), __expf(ALPHA * s1p), 0.0f, 0.0f);
            g_e2[row] = make_float2(__expf(s2p), __expf(ALPHA * s2p));
        }
    }
}

// ---------------------------------------------------------------------------
// Kernel 2: attention (R12, unchanged — at the legacy-HMMA rate ceiling).
// 1024 threads, 128x128 tile. mma: warp w: cc=w&7 -> rows cc*16, dd=w>>3 ->
// f-cols dd*32. pass-1: warp w owns rows {w,w+32,w+64,w+96}; lane owns
// j=4*lane..+3; p = mask ? max(E1*E2, F1*F2) : 0 (exp-free), via __ldg.
// One __syncthreads per tile; stage(T+1)+pass1(T+1) overlap mma(T).
// ---------------------------------------------------------------------------
__global__ void __launch_bounds__(1024, 1) attn_kernel(float* __restrict__ out)
{
    extern __shared__ char smc[];
    const unsigned HS_BYTES = 128 * 272;             // 34816
    const unsigned PS_OFF   = 2 * HS_BYTES;          // 69632
    const unsigned LS_OFF   = PS_OFF + 2 * HS_BYTES; // 139264

    unsigned* Ps32 = (unsigned*)(smc + PS_OFF);
    float*    l_s  = (float*)(smc + LS_OFF);         // [128]

    const unsigned smemBase = (unsigned)__cvta_generic_to_shared(smc);
    const unsigned psBase   = smemBase + PS_OFF;

    const int tid  = threadIdx.x;
    const int w    = tid >> 5;          // 0..31
    const int lane = tid & 31;
    const int cc   = w & 7;             // mma i-group
    const int dd   = w >> 3;            // mma f-block
    const int b    = blockIdx.y;
    const int i0   = blockIdx.x * 128;
    const int bN   = b * N_SZ;

    const __nv_bfloat16* hbb = g_hb + (size_t)bN * F_SZ;
    const float*         hbf = g_h  + (size_t)bN * F_SZ;

    // ---- pass-1 identity: rows w+32m, j = 4*lane..+3 ----
    float E1[4], F1[4];
#pragma unroll
    for (int m = 0; m < 4; m++) {
        float4 rc = g_rc[bN + i0 + w + 32 * m];
        E1[m] = rc.x; F1[m] = rc.y;
    }
    const unsigned* mbase0 = g_adjbits + (size_t)(i0 + w) * 64 + (lane >> 3);
    const float2*   e2b    = g_e2 + bN + 4 * lane;     // + T*128 (+2 for 2nd float4)
    const unsigned  sh0    = 4u * (unsigned)(lane & 7);

    // ---- mma ldmatrix addresses ----
    const unsigned aOff  = psBase + (unsigned)(cc * 16 + (lane & 15)) * 272
                         + (unsigned)(lane >> 4) * 16;
    const unsigned bRow  = (unsigned)(lane & 15) * 272;
    const unsigned bCol0 = (unsigned)(dd * 32 + (lane >> 4) * 8) * 2;
    const unsigned bCol1 = bCol0 + 32;

    float acc[4][4];
#pragma unroll
    for (int n = 0; n < 4; n++)
#pragma unroll
        for (int r = 0; r < 4; r++) acc[n][r] = 0.0f;
    float lacc[4] = {0.f, 0.f, 0.f, 0.f};

    // ---- staging: tile T (128x128 bf16 = 32KB) via 2 cp.async per thread ----
    auto stage = [&](int T, int buf) {
        unsigned dbase = smemBase + (unsigned)buf * HS_BYTES;
#pragma unroll
        for (int kk = 0; kk < 2; kk++) {
            int idx = kk * 1024 + tid;
            int row = idx >> 4, c16 = idx & 15;
            unsigned dst = dbase + (unsigned)row * 272 + (unsigned)c16 * 16;
            const void* src = hbb + (size_t)(T * 128 + row) * F_SZ + c16 * 8;
            asm volatile("cp.async.cg.shared.global [%0], [%1], 16;" :: "r"(dst), "l"(src));
        }
        asm volatile("cp.async.commit_group;");
    };

    // ---- pass 1 for tile T into Ps[buf] ----
    auto pass1 = [&](int T, int buf) {
        unsigned mw[4];
#pragma unroll
        for (int m = 0; m < 4; m++) mw[m] = __ldg(mbase0 + m * 32 * 64 + 4 * T);
        float4 ef0 = __ldg((const float4*)(e2b + T * 128));       // j=4l, 4l+1
        float4 ef1 = __ldg((const float4*)(e2b + T * 128 + 2));   // j=4l+2, 4l+3
        unsigned* psb = Ps32 + buf * 8704 + 2 * lane;
#pragma unroll
        for (int m = 0; m < 4; m++) {
            unsigned bits = (mw[m] >> sh0) & 0xFu;
            float pa0 = fmaxf(E1[m] * ef0.x, F1[m] * ef0.y);
            float pb0 = fmaxf(E1[m] * ef0.z, F1[m] * ef0.w);
            float pa1 = fmaxf(E1[m] * ef1.x, F1[m] * ef1.y);
            float pb1 = fmaxf(E1[m] * ef1.z, F1[m] * ef1.w);
            pa0 = (bits & 1u) ? pa0 : 0.0f;
            pb0 = (bits & 2u) ? pb0 : 0.0f;
            pa1 = (bits & 4u) ? pa1 : 0.0f;
            pb1 = (bits & 8u) ? pb1 : 0.0f;
            __nv_bfloat162 q0 = __floats2bfloat162_rn(pa0, pb0);
            __nv_bfloat162 q1 = __floats2bfloat162_rn(pa1, pb1);
            uint2 qq = make_uint2(*(unsigned*)&q0, *(unsigned*)&q1);
            *(uint2*)(psb + (w + 32 * m) * 68) = qq;
            lacc[m] += (pa0 + pb0) + (pa1 + pb1);
        }
    };

    // ---- prologue: tile 0 ----
    stage(0, 0);
    pass1(0, 0);
    asm volatile("cp.async.wait_group 0;");

    for (int T = 0; T < 16; T++) {
        const int buf = T & 1;
        __syncthreads();   // Ps[buf], Hs[buf] (tile T) visible to all warps

        if (T < 15) {
            stage(T + 1, buf ^ 1);
            pass1(T + 1, buf ^ 1);
        }

        // ---- mma(T): ACC += P[cc-group] @ H[:, dd-slab] ----
        const unsigned hsB = smemBase + (unsigned)buf * HS_BYTES;
        const unsigned psB = (unsigned)buf * HS_BYTES;
#pragma unroll
        for (int k = 0; k < 8; k++) {
            unsigned af[4];
            {
                unsigned addr = aOff + psB + (unsigned)k * 32;
                asm volatile("ldmatrix.sync.aligned.m8n8.x4.shared.b16 {%0,%1,%2,%3}, [%4];"
                             : "=r"(af[0]), "=r"(af[1]), "=r"(af[2]), "=r"(af[3])
                             : "r"(addr));
            }
            unsigned bb[2][4];
            {
                unsigned addr = hsB + bRow + (unsigned)k * 16 * 272 + bCol0;
                asm volatile("ldmatrix.sync.aligned.m8n8.x4.trans.shared.b16 {%0,%1,%2,%3}, [%4];"
                             : "=r"(bb[0][0]), "=r"(bb[0][1]), "=r"(bb[0][2]), "=r"(bb[0][3])
                             : "r"(addr));
                addr = hsB + bRow + (unsigned)k * 16 * 272 + bCol1;
                asm volatile("ldmatrix.sync.aligned.m8n8.x4.trans.shared.b16 {%0,%1,%2,%3}, [%4];"
                             : "=r"(bb[1][0]), "=r"(bb[1][1]), "=r"(bb[1][2]), "=r"(bb[1][3])
                             : "r"(addr));
            }
#pragma unroll
            for (int n = 0; n < 4; n++) {
                asm volatile(
                    "mma.sync.aligned.m16n8k16.row.col.f32.bf16.bf16.f32 "
                    "{%0,%1,%2,%3}, {%4,%5,%6,%7}, {%8,%9}, {%0,%1,%2,%3};"
                    : "+f"(acc[n][0]), "+f"(acc[n][1]),
                      "+f"(acc[n][2]), "+f"(acc[n][3])
                    : "r"(af[0]), "r"(af[1]), "r"(af[2]), "r"(af[3]),
                      "r"(bb[n >> 1][2 * (n & 1)]), "r"(bb[n >> 1][2 * (n & 1) + 1]));
            }
        }

        asm volatile("cp.async.wait_group 0;");   // own stage(T+1) copies landed
    }

    // ---- l: full warp reduce (each row owned by exactly one warp) ----
#pragma unroll
    for (int m = 0; m < 4; m++) {
#pragma unroll
        for (int o = 16; o; o >>= 1) lacc[m] += __shfl_xor_sync(0xffffffffu, lacc[m], o);
        if (lane == 0) l_s[w + 32 * m] = lacc[m];
    }
    __syncthreads();

    // ---- epilogue: normalize, +residual, elu ----
#pragma unroll
    for (int rp = 0; rp < 2; rp++) {
        int rl = cc * 16 + (lane >> 2) + 8 * rp;
        float invl = 1.0f / l_s[rl];
        int i = i0 + rl;
#pragma unroll
        for (int n = 0; n < 4; n++) {
            int col = dd * 32 + n * 8 + (lane & 3) * 2;
            const float2 r = *(const float2*)(hbf + (size_t)i * F_SZ + col);
            float ox = acc[n][2 * rp]     * invl + r.x;
            float oy = acc[n][2 * rp + 1] * invl + r.y;
            ox = ox > 0.0f ? ox : __expf(ox) - 1.0f;
            oy = oy > 0.0f ? oy : __expf(oy) - 1.0f;
            *(float2*)(out + ((size_t)bN + i) * F_SZ + col) = make_float2(ox, oy);
        }
    }
}

// ---------------------------------------------------------------------------
extern "C" void kernel_launch(void* const* d_in, const int* in_sizes, int n_in,
                              void* d_out, int out_size)
{
    const float* x     = (const float*)d_in[0];
    const int*   adj   = (const int*)d_in[1];
    const float* W     = (const float*)d_in[2];
    const float* a     = (const float*)d_in[3];
    const float* nw    = (const float*)d_in[4];
    const float* nb    = (const float*)d_in[5];
    const float* gamma = (const float*)d_in[6];
    const float* beta  = (const float*)d_in[7];
    float* out = (float*)d_out;

    const int prep_smem = (16384 + 4096 + 4 * 128) * 4;       // 83968 B
    const int attn_smem = 139264 + 512;                        // 139776 B
    cudaFuncSetAttribute(prep_kernel, cudaFuncAttributeMaxDynamicSharedMemorySize, prep_smem);
    cudaFuncSetAttribute(attn_kernel, cudaFuncAttributeMaxDynamicSharedMemorySize, attn_smem);

    prep_kernel<<<1024, 256, prep_smem>>>(x, adj, W, a, nw, nb, gamma, beta);

    dim3 grid(N_SZ / 128, B_SZ);
    attn_kernel<<<grid, 1024, attn_smem>>>(out);
}

// round 15
// speedup vs baseline: 1.0984x; 1.0004x over previous
#include <cuda_runtime.h>
#include <cuda_bf16.h>
#include <math.h>

#define B_SZ 8
#define N_SZ 2048
#define F_SZ 128
#define ROWS_TOTAL (B_SZ * N_SZ)
#define ALPHA 0.2f
#define LN_EPS 1e-5f

// Scratch (__device__ globals: allocation-free rule)
__device__ float          g_h [ROWS_TOTAL * F_SZ];   // post-LN h fp32 (residual)
__device__ __nv_bfloat16  g_hb[ROWS_TOTAL * F_SZ];   // post-LN h bf16 (mma B operand)
__device__ float4         g_rc[ROWS_TOTAL];          // {exp(s1), exp(a*s1), -, -}
__device__ float2         g_e2[ROWS_TOTAL];          // {exp(s2), exp(a*s2)}
__device__ unsigned       g_adjbits[N_SZ * (N_SZ / 32)];

// ---------------------------------------------------------------------------
// Kernel 1 (512 threads, 2 CTAs/SM -> ~2 waves total):
//   blocks [0,256): prep, 64 rows/block, 16 warps (8/SMSP latency cover).
//   blocks [256,512): pack adj -> bitmask, 1 word/thread, 8 batched int4.
// ---------------------------------------------------------------------------
__global__ void __launch_bounds__(512, 2) prep_kernel(
    const float* __restrict__ x, const int* __restrict__ adj,
    const float* __restrict__ W, const float* __restrict__ a,
    const float* __restrict__ nw, const float* __restrict__ nb,
    const float* __restrict__ gamma, const float* __restrict__ beta)
{
    const int tid = threadIdx.x;
    if (blockIdx.x >= 256) {                               // ---- pack ----
        int gid = (blockIdx.x - 256) * 512 + tid;
        const int4* src = (const int4*)adj + (size_t)gid * 8;
        int4 v[8];
#pragma unroll
        for (int u = 0; u < 8; u++) v[u] = src[u];          // 8 independent LDG.128
        unsigned bits = 0;
#pragma unroll
        for (int u = 0; u < 8; u++) {
            bits |= (v[u].x > 0 ? 1u : 0u) << (4 * u);
            bits |= (v[u].y > 0 ? 1u : 0u) << (4 * u + 1);
            bits |= (v[u].z > 0 ? 1u : 0u) << (4 * u + 2);
            bits |= (v[u].w > 0 ? 1u : 0u) << (4 * u + 3);
        }
        g_adjbits[gid] = bits;
        return;
    }

    extern __shared__ float sm[];
    float* Ws  = sm;               // 16384
    float* xs  = sm + 16384;       // 64*128 = 8192
    float* a1s = xs + 8192;        // 128
    float* a2s = a1s + 128;        // 128
    float* gs  = a2s + 128;        // 128
    float* bs  = gs + 128;         // 128

    const int row0 = blockIdx.x * 64;

#pragma unroll
    for (int k = 0; k < 32; k++) Ws[k * 512 + tid] = W[k * 512 + tid];
#pragma unroll
    for (int k = 0; k < 16; k++) {
        int idx = k * 512 + tid;
        int rl = idx >> 7, f = idx & 127;
        int row = row0 + rl;
        int n = row & (N_SZ - 1);
        xs[idx] = x[(size_t)row * F_SZ + f] * (1.0f + nw[n]) + nb[n];
    }
    if (tid < 128) {
        a1s[tid] = a[tid];
        a2s[tid] = a[128 + tid];
        gs[tid]  = gamma[tid];
        bs[tid]  = beta[tid];
    }
    __syncthreads();

    const int w = tid >> 5, lane = tid & 31;   // w: 0..15
    const int rbase = w * 4;
    float acc[4][4];
#pragma unroll
    for (int r = 0; r < 4; r++)
#pragma unroll
        for (int k = 0; k < 4; k++) acc[r][k] = 0.0f;

#pragma unroll 2
    for (int f = 0; f < 128; f++) {
        float w0 = Ws[f * 128 + lane];
        float w1 = Ws[f * 128 + 32 + lane];
        float w2 = Ws[f * 128 + 64 + lane];
        float w3 = Ws[f * 128 + 96 + lane];
#pragma unroll
        for (int r = 0; r < 4; r++) {
            float xv = xs[(rbase + r) * 128 + f];
            acc[r][0] += xv * w0;
            acc[r][1] += xv * w1;
            acc[r][2] += xv * w2;
            acc[r][3] += xv * w3;
        }
    }

#pragma unroll
    for (int r = 0; r < 4; r++) {
        int row = row0 + rbase + r;
        float s = acc[r][0] + acc[r][1] + acc[r][2] + acc[r][3];
#pragma unroll
        for (int o = 16; o; o >>= 1) s += __shfl_xor_sync(0xffffffffu, s, o);
        float mu = s * 0.0078125f;
        float d0 = acc[r][0] - mu, d1 = acc[r][1] - mu;
        float d2 = acc[r][2] - mu, d3 = acc[r][3] - mu;
        float v = d0 * d0 + d1 * d1 + d2 * d2 + d3 * d3;
#pragma unroll
        for (int o = 16; o; o >>= 1) v += __shfl_xor_sync(0xffffffffu, v, o);
        float rstd = rsqrtf(v * 0.0078125f + LN_EPS);
        float h0 = d0 * rstd * gs[lane]      + bs[lane];
        float h1 = d1 * rstd * gs[32 + lane] + bs[32 + lane];
        float h2 = d2 * rstd * gs[64 + lane] + bs[64 + lane];
        float h3 = d3 * rstd * gs[96 + lane] + bs[96 + lane];
        float s1p = h0 * a1s[lane] + h1 * a1s[32 + lane] + h2 * a1s[64 + lane] + h3 * a1s[96 + lane];
        float s2p = h0 * a2s[lane] + h1 * a2s[32 + lane] + h2 * a2s[64 + lane] + h3 * a2s[96 + lane];
#pragma unroll
        for (int o = 16; o; o >>= 1) {
            s1p += __shfl_xor_sync(0xffffffffu, s1p, o);
            s2p += __shfl_xor_sync(0xffffffffu, s2p, o);
        }
        size_t ro = (size_t)row * F_SZ;
        g_h[ro + lane]      = h0;
        g_h[ro + 32 + lane] = h1;
        g_h[ro + 64 + lane] = h2;
        g_h[ro + 96 + lane] = h3;
        g_hb[ro + lane]      = __float2bfloat16(h0);
        g_hb[ro + 32 + lane] = __float2bfloat16(h1);
        g_hb[ro + 64 + lane] = __float2bfloat16(h2);
        g_hb[ro + 96 + lane] = __float2bfloat16(h3);
        if (lane == 0) {
            g_rc[row] = make_float4(__expf(s1p), __expf(ALPHA * s1p), 0.0f, 0.0f);
            g_e2[row] = make_float2(__expf(s2p), __expf(ALPHA * s2p));
        }
    }
}

// ---------------------------------------------------------------------------
// Kernel 2: attention (R12/R14, unchanged — at the legacy-HMMA rate ceiling).
// 1024 threads, 128x128 tile. mma: warp w: cc=w&7 -> rows cc*16, dd=w>>3 ->
// f-cols dd*32. pass-1: warp w owns rows {w,w+32,w+64,w+96}; lane owns
// j=4*lane..+3; p = mask ? max(E1*E2, F1*F2) : 0 (exp-free), via __ldg.
// One __syncthreads per tile; stage(T+1)+pass1(T+1) overlap mma(T).
// ---------------------------------------------------------------------------
__global__ void __launch_bounds__(1024, 1) attn_kernel(float* __restrict__ out)
{
    extern __shared__ char smc[];
    const unsigned HS_BYTES = 128 * 272;             // 34816
    const unsigned PS_OFF   = 2 * HS_BYTES;          // 69632
    const unsigned LS_OFF   = PS_OFF + 2 * HS_BYTES; // 139264

    unsigned* Ps32 = (unsigned*)(smc + PS_OFF);
    float*    l_s  = (float*)(smc + LS_OFF);         // [128]

    const unsigned smemBase = (unsigned)__cvta_generic_to_shared(smc);
    const unsigned psBase   = smemBase + PS_OFF;

    const int tid  = threadIdx.x;
    const int w    = tid >> 5;          // 0..31
    const int lane = tid & 31;
    const int cc   = w & 7;             // mma i-group
    const int dd   = w >> 3;            // mma f-block
    const int b    = blockIdx.y;
    const int i0   = blockIdx.x * 128;
    const int bN   = b * N_SZ;

    const __nv_bfloat16* hbb = g_hb + (size_t)bN * F_SZ;
    const float*         hbf = g_h  + (size_t)bN * F_SZ;

    // ---- pass-1 identity: rows w+32m, j = 4*lane..+3 ----
    float E1[4], F1[4];
#pragma unroll
    for (int m = 0; m < 4; m++) {
        float4 rc = g_rc[bN + i0 + w + 32 * m];
        E1[m] = rc.x; F1[m] = rc.y;
    }
    const unsigned* mbase0 = g_adjbits + (size_t)(i0 + w) * 64 + (lane >> 3);
    const float2*   e2b    = g_e2 + bN + 4 * lane;     // + T*128 (+2 for 2nd float4)
    const unsigned  sh0    = 4u * (unsigned)(lane & 7);

    // ---- mma ldmatrix addresses ----
    const unsigned aOff  = psBase + (unsigned)(cc * 16 + (lane & 15)) * 272
                         + (unsigned)(lane >> 4) * 16;
    const unsigned bRow  = (unsigned)(lane & 15) * 272;
    const unsigned bCol0 = (unsigned)(dd * 32 + (lane >> 4) * 8) * 2;
    const unsigned bCol1 = bCol0 + 32;

    float acc[4][4];
#pragma unroll
    for (int n = 0; n < 4; n++)
#pragma unroll
        for (int r = 0; r < 4; r++) acc[n][r] = 0.0f;
    float lacc[4] = {0.f, 0.f, 0.f, 0.f};

    // ---- staging: tile T (128x128 bf16 = 32KB) via 2 cp.async per thread ----
    auto stage = [&](int T, int buf) {
        unsigned dbase = smemBase + (unsigned)buf * HS_BYTES;
#pragma unroll
        for (int kk = 0; kk < 2; kk++) {
            int idx = kk * 1024 + tid;
            int row = idx >> 4, c16 = idx & 15;
            unsigned dst = dbase + (unsigned)row * 272 + (unsigned)c16 * 16;
            const void* src = hbb + (size_t)(T * 128 + row) * F_SZ + c16 * 8;
            asm volatile("cp.async.cg.shared.global [%0], [%1], 16;" :: "r"(dst), "l"(src));
        }
        asm volatile("cp.async.commit_group;");
    };

    // ---- pass 1 for tile T into Ps[buf] ----
    auto pass1 = [&](int T, int buf) {
        unsigned mw[4];
#pragma unroll
        for (int m = 0; m < 4; m++) mw[m] = __ldg(mbase0 + m * 32 * 64 + 4 * T);
        float4 ef0 = __ldg((const float4*)(e2b + T * 128));       // j=4l, 4l+1
        float4 ef1 = __ldg((const float4*)(e2b + T * 128 + 2));   // j=4l+2, 4l+3
        unsigned* psb = Ps32 + buf * 8704 + 2 * lane;
#pragma unroll
        for (int m = 0; m < 4; m++) {
            unsigned bits = (mw[m] >> sh0) & 0xFu;
            float pa0 = fmaxf(E1[m] * ef0.x, F1[m] * ef0.y);
            float pb0 = fmaxf(E1[m] * ef0.z, F1[m] * ef0.w);
            float pa1 = fmaxf(E1[m] * ef1.x, F1[m] * ef1.y);
            float pb1 = fmaxf(E1[m] * ef1.z, F1[m] * ef1.w);
            pa0 = (bits & 1u) ? pa0 : 0.0f;
            pb0 = (bits & 2u) ? pb0 : 0.0f;
            pa1 = (bits & 4u) ? pa1 : 0.0f;
            pb1 = (bits & 8u) ? pb1 : 0.0f;
            __nv_bfloat162 q0 = __floats2bfloat162_rn(pa0, pb0);
            __nv_bfloat162 q1 = __floats2bfloat162_rn(pa1, pb1);
            uint2 qq = make_uint2(*(unsigned*)&q0, *(unsigned*)&q1);
            *(uint2*)(psb + (w + 32 * m) * 68) = qq;
            lacc[m] += (pa0 + pb0) + (pa1 + pb1);
        }
    };

    // ---- prologue: tile 0 ----
    stage(0, 0);
    pass1(0, 0);
    asm volatile("cp.async.wait_group 0;");

    for (int T = 0; T < 16; T++) {
        const int buf = T & 1;
        __syncthreads();   // Ps[buf], Hs[buf] (tile T) visible to all warps

        if (T < 15) {
            stage(T + 1, buf ^ 1);
            pass1(T + 1, buf ^ 1);
        }

        // ---- mma(T): ACC += P[cc-group] @ H[:, dd-slab] ----
        const unsigned hsB = smemBase + (unsigned)buf * HS_BYTES;
        const unsigned psB = (unsigned)buf * HS_BYTES;
#pragma unroll
        for (int k = 0; k < 8; k++) {
            unsigned af[4];
            {
                unsigned addr = aOff + psB + (unsigned)k * 32;
                asm volatile("ldmatrix.sync.aligned.m8n8.x4.shared.b16 {%0,%1,%2,%3}, [%4];"
                             : "=r"(af[0]), "=r"(af[1]), "=r"(af[2]), "=r"(af[3])
                             : "r"(addr));
            }
            unsigned bb[2][4];
            {
                unsigned addr = hsB + bRow + (unsigned)k * 16 * 272 + bCol0;
                asm volatile("ldmatrix.sync.aligned.m8n8.x4.trans.shared.b16 {%0,%1,%2,%3}, [%4];"
                             : "=r"(bb[0][0]), "=r"(bb[0][1]), "=r"(bb[0][2]), "=r"(bb[0][3])
                             : "r"(addr));
                addr = hsB + bRow + (unsigned)k * 16 * 272 + bCol1;
                asm volatile("ldmatrix.sync.aligned.m8n8.x4.trans.shared.b16 {%0,%1,%2,%3}, [%4];"
                             : "=r"(bb[1][0]), "=r"(bb[1][1]), "=r"(bb[1][2]), "=r"(bb[1][3])
                             : "r"(addr));
            }
#pragma unroll
            for (int n = 0; n < 4; n++) {
                asm volatile(
                    "mma.sync.aligned.m16n8k16.row.col.f32.bf16.bf16.f32 "
                    "{%0,%1,%2,%3}, {%4,%5,%6,%7}, {%8,%9}, {%0,%1,%2,%3};"
                    : "+f"(acc[n][0]), "+f"(acc[n][1]),
                      "+f"(acc[n][2]), "+f"(acc[n][3])
                    : "r"(af[0]), "r"(af[1]), "r"(af[2]), "r"(af[3]),
                      "r"(bb[n >> 1][2 * (n & 1)]), "r"(bb[n >> 1][2 * (n & 1) + 1]));
            }
        }

        asm volatile("cp.async.wait_group 0;");   // own stage(T+1) copies landed
    }

    // ---- l: full warp reduce (each row owned by exactly one warp) ----
#pragma unroll
    for (int m = 0; m < 4; m++) {
#pragma unroll
        for (int o = 16; o; o >>= 1) lacc[m] += __shfl_xor_sync(0xffffffffu, lacc[m], o);
        if (lane == 0) l_s[w + 32 * m] = lacc[m];
    }
    __syncthreads();

    // ---- epilogue: normalize, +residual, elu ----
#pragma unroll
    for (int rp = 0; rp < 2; rp++) {
        int rl = cc * 16 + (lane >> 2) + 8 * rp;
        float invl = 1.0f / l_s[rl];
        int i = i0 + rl;
#pragma unroll
        for (int n = 0; n < 4; n++) {
            int col = dd * 32 + n * 8 + (lane & 3) * 2;
            const float2 r = *(const float2*)(hbf + (size_t)i * F_SZ + col);
            float ox = acc[n][2 * rp]     * invl + r.x;
            float oy = acc[n][2 * rp + 1] * invl + r.y;
            ox = ox > 0.0f ? ox : __expf(ox) - 1.0f;
            oy = oy > 0.0f ? oy : __expf(oy) - 1.0f;
            *(float2*)(out + ((size_t)bN + i) * F_SZ + col) = make_float2(ox, oy);
        }
    }
}

// ---------------------------------------------------------------------------
extern "C" void kernel_launch(void* const* d_in, const int* in_sizes, int n_in,
                              void* d_out, int out_size)
{
    const float* x     = (const float*)d_in[0];
    const int*   adj   = (const int*)d_in[1];
    const float* W     = (const float*)d_in[2];
    const float* a     = (const float*)d_in[3];
    const float* nw    = (const float*)d_in[4];
    const float* nb    = (const float*)d_in[5];
    const float* gamma = (const float*)d_in[6];
    const float* beta  = (const float*)d_in[7];
    float* out = (float*)d_out;

    const int prep_smem = (16384 + 8192 + 4 * 128) * 4;       // 100352 B (x2 = 200KB/SM OK)
    const int attn_smem = 139264 + 512;                        // 139776 B
    cudaFuncSetAttribute(prep_kernel, cudaFuncAttributeMaxDynamicSharedMemorySize, prep_smem);
    cudaFuncSetAttribute(attn_kernel, cudaFuncAttributeMaxDynamicSharedMemorySize, attn_smem);

    prep_kernel<<<512, 512, prep_smem>>>(x, adj, W, a, nw, nb, gamma, beta);

    dim3 grid(N_SZ / 128, B_SZ);
    attn_kernel<<<grid, 1024, attn_smem>>>(out);
}

// round 16
// speedup vs baseline: 1.2725x; 1.1586x over previous
#include <cuda_runtime.h>
#include <cuda_bf16.h>
#include <math.h>

#define B_SZ 8
#define N_SZ 2048
#define F_SZ 128
#define ROWS_TOTAL (B_SZ * N_SZ)
#define ALPHA 0.2f
#define LN_EPS 1e-5f

// Scratch (__device__ globals: allocation-free rule)
__device__ float          g_h [ROWS_TOTAL * F_SZ];   // post-LN h fp32 (residual)
__device__ __nv_bfloat16  g_hb[ROWS_TOTAL * F_SZ];   // post-LN h bf16 (mma B operand)
__device__ float4         g_rc[ROWS_TOTAL];          // {exp(s1), exp(a*s1), -, -}
__device__ float2         g_e2[ROWS_TOTAL];          // {exp(s2), exp(a*s2)}
__device__ unsigned       g_adjbits[N_SZ * (N_SZ / 32)];

__device__ __forceinline__ unsigned f2tf(float f) {
    unsigned u;
    asm("cvt.rna.tf32.f32 %0, %1;" : "=r"(u) : "f"(f));
    return u;
}

// ---------------------------------------------------------------------------
// Kernel 1: blocks [0,256): prep via tf32 tensor cores — h = x'@W on mma
//   (R2-validated fragment layout), then cross-warp LN + s1/s2 reduction.
//   blocks [256,768): pack adj -> bitmask, 1 word/thread, 8 batched int4.
// ---------------------------------------------------------------------------
__global__ void __launch_bounds__(256, 2) prep_kernel(
    const float* __restrict__ x, const int* __restrict__ adj,
    const float* __restrict__ W, const float* __restrict__ a,
    const float* __restrict__ nw, const float* __restrict__ nb,
    const float* __restrict__ gamma, const float* __restrict__ beta)
{
    const int tid = threadIdx.x;
    if (blockIdx.x >= 256) {                               // ---- pack ----
        int gid = (blockIdx.x - 256) * 256 + tid;
        const int4* src = (const int4*)adj + (size_t)gid * 8;
        int4 v[8];
#pragma unroll
        for (int u = 0; u < 8; u++) v[u] = src[u];
        unsigned bits = 0;
#pragma unroll
        for (int u = 0; u < 8; u++) {
            bits |= (v[u].x > 0 ? 1u : 0u) << (4 * u);
            bits |= (v[u].y > 0 ? 1u : 0u) << (4 * u + 1);
            bits |= (v[u].z > 0 ? 1u : 0u) << (4 * u + 2);
            bits |= (v[u].w > 0 ? 1u : 0u) << (4 * u + 3);
        }
        g_adjbits[gid] = bits;
        return;
    }

    extern __shared__ float sm[];
    unsigned* Ws  = (unsigned*)sm;            // [128][136] tf32 = 17408 words
    unsigned* xp  = (unsigned*)(sm + 17408);  // [64][132] tf32 = 8448 words
    float* a1s = sm + 25856;                  // 128
    float* a2s = sm + 25984;                  // 128
    float* gs  = sm + 26112;                  // 128
    float* bs  = sm + 26240;                  // 128
    float* rsum = sm + 26368;                 // [64][4]
    float* rssq = sm + 26624;                 // [64][4]
    float* sp1  = sm + 26880;                 // [64][4]
    float* sp2  = sm + 27136;                 // [64][4]  -> total 27392 f = 109568 B

    const int row0 = blockIdx.x * 64;

    // stage W -> tf32 smem [f][o]
#pragma unroll
    for (int k = 0; k < 64; k++) {
        int idx = k * 256 + tid;
        int f = idx >> 7, o = idx & 127;
        Ws[f * 136 + o] = f2tf(W[idx]);
    }
    // stage x' -> tf32 smem [row][f]
#pragma unroll
    for (int k = 0; k < 32; k++) {
        int idx = k * 256 + tid;
        int rl = idx >> 7, f = idx & 127;
        int row = row0 + rl;
        int n = row & (N_SZ - 1);
        xp[rl * 132 + f] = f2tf(x[(size_t)row * F_SZ + f] * (1.0f + nw[n]) + nb[n]);
    }
    if (tid < 128) {
        a1s[tid] = a[tid];
        a2s[tid] = a[128 + tid];
        gs[tid]  = gamma[tid];
        bs[tid]  = beta[tid];
    }
    __syncthreads();

    const int w = tid >> 5, lane = tid & 31;
    const int g = lane >> 2, t = lane & 3;
    const int ib = (w & 1) * 32;     // i-block
    const int fb = (w >> 1) * 32;    // o-block
    const int fi = w >> 1;           // o-block index 0..3

    float acc[2][4][4];
#pragma unroll
    for (int ig = 0; ig < 2; ig++)
#pragma unroll
        for (int n = 0; n < 4; n++)
#pragma unroll
            for (int r = 0; r < 4; r++) acc[ig][n][r] = 0.0f;

    // ---- mma: h[64x128] = xp[64x128] @ Ws[128x128] (tf32, R2 layout) ----
#pragma unroll 4
    for (int k = 0; k < 16; k++) {
        unsigned a0[2], a1r[2], a2r[2], a3r[2];
#pragma unroll
        for (int ig = 0; ig < 2; ig++) {
            const unsigned* pr = xp + (ib + ig * 16 + g) * 132 + k * 8 + t;
            a0[ig] = pr[0];
            a2r[ig] = pr[4];
            const unsigned* pr8 = pr + 8 * 132;
            a1r[ig] = pr8[0];
            a3r[ig] = pr8[4];
        }
        unsigned b0[4], b1[4];
#pragma unroll
        for (int n = 0; n < 4; n++) {
            const unsigned* hr = Ws + (k * 8 + t) * 136 + fb + n * 8 + g;
            b0[n] = hr[0];
            b1[n] = hr[4 * 136];
        }
#pragma unroll
        for (int ig = 0; ig < 2; ig++)
#pragma unroll
            for (int n = 0; n < 4; n++) {
                asm volatile(
                    "mma.sync.aligned.m16n8k8.row.col.f32.tf32.tf32.f32 "
                    "{%0,%1,%2,%3}, {%4,%5,%6,%7}, {%8,%9}, {%0,%1,%2,%3};"
                    : "+f"(acc[ig][n][0]), "+f"(acc[ig][n][1]),
                      "+f"(acc[ig][n][2]), "+f"(acc[ig][n][3])
                    : "r"(a0[ig]), "r"(a1r[ig]), "r"(a2r[ig]), "r"(a3r[ig]),
                      "r"(b0[n]), "r"(b1[n]));
            }
    }

    // ---- LN partials: acc[ig][n][2rp+c] -> row ib+ig*16+g+8rp, col fb+n*8+2t+c
#pragma unroll
    for (int ig = 0; ig < 2; ig++)
#pragma unroll
        for (int rp = 0; rp < 2; rp++) {
            float s = 0.0f, ss = 0.0f;
#pragma unroll
            for (int n = 0; n < 4; n++) {
                float u0 = acc[ig][n][2 * rp], u1 = acc[ig][n][2 * rp + 1];
                s += u0 + u1;
                ss += u0 * u0 + u1 * u1;
            }
            s  += __shfl_xor_sync(0xffffffffu, s, 1);
            s  += __shfl_xor_sync(0xffffffffu, s, 2);
            ss += __shfl_xor_sync(0xffffffffu, ss, 1);
            ss += __shfl_xor_sync(0xffffffffu, ss, 2);
            if (t == 0) {
                int r = ib + ig * 16 + g + 8 * rp;
                rsum[r * 4 + fi] = s;
                rssq[r * 4 + fi] = ss;
            }
        }
    __syncthreads();

    // ---- normalize + store h + s1/s2 partials ----
#pragma unroll
    for (int ig = 0; ig < 2; ig++)
#pragma unroll
        for (int rp = 0; rp < 2; rp++) {
            int r = ib + ig * 16 + g + 8 * rp;
            float S  = rsum[r * 4] + rsum[r * 4 + 1] + rsum[r * 4 + 2] + rsum[r * 4 + 3];
            float SS = rssq[r * 4] + rssq[r * 4 + 1] + rssq[r * 4 + 2] + rssq[r * 4 + 3];
            float mu = S * 0.0078125f;
            float var = SS * 0.0078125f - mu * mu;
            float rstd = rsqrtf(var + LN_EPS);
            int row = row0 + r;
            float s1p = 0.0f, s2p = 0.0f;
#pragma unroll
            for (int n = 0; n < 4; n++) {
                int col = fb + n * 8 + t * 2;
                float h0 = (acc[ig][n][2 * rp]     - mu) * rstd * gs[col]     + bs[col];
                float h1 = (acc[ig][n][2 * rp + 1] - mu) * rstd * gs[col + 1] + bs[col + 1];
                size_t off = (size_t)row * F_SZ + col;
                *(float2*)(g_h + off) = make_float2(h0, h1);
                __nv_bfloat162 hb = __floats2bfloat162_rn(h0, h1);
                *(__nv_bfloat162*)(g_hb + off) = hb;
                s1p += h0 * a1s[col] + h1 * a1s[col + 1];
                s2p += h0 * a2s[col] + h1 * a2s[col + 1];
            }
            s1p += __shfl_xor_sync(0xffffffffu, s1p, 1);
            s1p += __shfl_xor_sync(0xffffffffu, s1p, 2);
            s2p += __shfl_xor_sync(0xffffffffu, s2p, 1);
            s2p += __shfl_xor_sync(0xffffffffu, s2p, 2);
            if (t == 0) {
                sp1[r * 4 + fi] = s1p;
                sp2[r * 4 + fi] = s2p;
            }
        }
    __syncthreads();

    // ---- score factors (rows covered by fi==0 warps: w=0 -> rows 0..31, w=1 -> 32..63)
    if (fi == 0 && t == 0) {
#pragma unroll
        for (int ig = 0; ig < 2; ig++)
#pragma unroll
            for (int rp = 0; rp < 2; rp++) {
                int r = ib + ig * 16 + g + 8 * rp;
                float s1 = sp1[r * 4] + sp1[r * 4 + 1] + sp1[r * 4 + 2] + sp1[r * 4 + 3];
                float s2 = sp2[r * 4] + sp2[r * 4 + 1] + sp2[r * 4 + 2] + sp2[r * 4 + 3];
                int row = row0 + r;
                g_rc[row] = make_float4(__expf(s1), __expf(ALPHA * s1), 0.0f, 0.0f);
                g_e2[row] = make_float2(__expf(s2), __expf(ALPHA * s2));
            }
    }
}

// ---------------------------------------------------------------------------
// Kernel 2: attention (R12/R14, unchanged — at the legacy-HMMA rate ceiling).
// ---------------------------------------------------------------------------
__global__ void __launch_bounds__(1024, 1) attn_kernel(float* __restrict__ out)
{
    extern __shared__ char smc[];
    const unsigned HS_BYTES = 128 * 272;             // 34816
    const unsigned PS_OFF   = 2 * HS_BYTES;          // 69632
    const unsigned LS_OFF   = PS_OFF + 2 * HS_BYTES; // 139264

    unsigned* Ps32 = (unsigned*)(smc + PS_OFF);
    float*    l_s  = (float*)(smc + LS_OFF);         // [128]

    const unsigned smemBase = (unsigned)__cvta_generic_to_shared(smc);
    const unsigned psBase   = smemBase + PS_OFF;

    const int tid  = threadIdx.x;
    const int w    = tid >> 5;          // 0..31
    const int lane = tid & 31;
    const int cc   = w & 7;             // mma i-group
    const int dd   = w >> 3;            // mma f-block
    const int b    = blockIdx.y;
    const int i0   = blockIdx.x * 128;
    const int bN   = b * N_SZ;

    const __nv_bfloat16* hbb = g_hb + (size_t)bN * F_SZ;
    const float*         hbf = g_h  + (size_t)bN * F_SZ;

    float E1[4], F1[4];
#pragma unroll
    for (int m = 0; m < 4; m++) {
        float4 rc = g_rc[bN + i0 + w + 32 * m];
        E1[m] = rc.x; F1[m] = rc.y;
    }
    const unsigned* mbase0 = g_adjbits + (size_t)(i0 + w) * 64 + (lane >> 3);
    const float2*   e2b    = g_e2 + bN + 4 * lane;
    const unsigned  sh0    = 4u * (unsigned)(lane & 7);

    const unsigned aOff  = psBase + (unsigned)(cc * 16 + (lane & 15)) * 272
                         + (unsigned)(lane >> 4) * 16;
    const unsigned bRow  = (unsigned)(lane & 15) * 272;
    const unsigned bCol0 = (unsigned)(dd * 32 + (lane >> 4) * 8) * 2;
    const unsigned bCol1 = bCol0 + 32;

    float acc[4][4];
#pragma unroll
    for (int n = 0; n < 4; n++)
#pragma unroll
        for (int r = 0; r < 4; r++) acc[n][r] = 0.0f;
    float lacc[4] = {0.f, 0.f, 0.f, 0.f};

    auto stage = [&](int T, int buf) {
        unsigned dbase = smemBase + (unsigned)buf * HS_BYTES;
#pragma unroll
        for (int kk = 0; kk < 2; kk++) {
            int idx = kk * 1024 + tid;
            int row = idx >> 4, c16 = idx & 15;
            unsigned dst = dbase + (unsigned)row * 272 + (unsigned)c16 * 16;
            const void* src = hbb + (size_t)(T * 128 + row) * F_SZ + c16 * 8;
            asm volatile("cp.async.cg.shared.global [%0], [%1], 16;" :: "r"(dst), "l"(src));
        }
        asm volatile("cp.async.commit_group;");
    };

    auto pass1 = [&](int T, int buf) {
        unsigned mw[4];
#pragma unroll
        for (int m = 0; m < 4; m++) mw[m] = __ldg(mbase0 + m * 32 * 64 + 4 * T);
        float4 ef0 = __ldg((const float4*)(e2b + T * 128));
        float4 ef1 = __ldg((const float4*)(e2b + T * 128 + 2));
        unsigned* psb = Ps32 + buf * 8704 + 2 * lane;
#pragma unroll
        for (int m = 0; m < 4; m++) {
            unsigned bits = (mw[m] >> sh0) & 0xFu;
            float pa0 = fmaxf(E1[m] * ef0.x, F1[m] * ef0.y);
            float pb0 = fmaxf(E1[m] * ef0.z, F1[m] * ef0.w);
            float pa1 = fmaxf(E1[m] * ef1.x, F1[m] * ef1.y);
            float pb1 = fmaxf(E1[m] * ef1.z, F1[m] * ef1.w);
            pa0 = (bits & 1u) ? pa0 : 0.0f;
            pb0 = (bits & 2u) ? pb0 : 0.0f;
            pa1 = (bits & 4u) ? pa1 : 0.0f;
            pb1 = (bits & 8u) ? pb1 : 0.0f;
            __nv_bfloat162 q0 = __floats2bfloat162_rn(pa0, pb0);
            __nv_bfloat162 q1 = __floats2bfloat162_rn(pa1, pb1);
            uint2 qq = make_uint2(*(unsigned*)&q0, *(unsigned*)&q1);
            *(uint2*)(psb + (w + 32 * m) * 68) = qq;
            lacc[m] += (pa0 + pb0) + (pa1 + pb1);
        }
    };

    stage(0, 0);
    pass1(0, 0);
    asm volatile("cp.async.wait_group 0;");

    for (int T = 0; T < 16; T++) {
        const int buf = T & 1;
        __syncthreads();

        if (T < 15) {
            stage(T + 1, buf ^ 1);
            pass1(T + 1, buf ^ 1);
        }

        const unsigned hsB = smemBase + (unsigned)buf * HS_BYTES;
        const unsigned psB = (unsigned)buf * HS_BYTES;
#pragma unroll
        for (int k = 0; k < 8; k++) {
            unsigned af[4];
            {
                unsigned addr = aOff + psB + (unsigned)k * 32;
                asm volatile("ldmatrix.sync.aligned.m8n8.x4.shared.b16 {%0,%1,%2,%3}, [%4];"
                             : "=r"(af[0]), "=r"(af[1]), "=r"(af[2]), "=r"(af[3])
                             : "r"(addr));
            }
            unsigned bb[2][4];
            {
                unsigned addr = hsB + bRow + (unsigned)k * 16 * 272 + bCol0;
                asm volatile("ldmatrix.sync.aligned.m8n8.x4.trans.shared.b16 {%0,%1,%2,%3}, [%4];"
                             : "=r"(bb[0][0]), "=r"(bb[0][1]), "=r"(bb[0][2]), "=r"(bb[0][3])
                             : "r"(addr));
                addr = hsB + bRow + (unsigned)k * 16 * 272 + bCol1;
                asm volatile("ldmatrix.sync.aligned.m8n8.x4.trans.shared.b16 {%0,%1,%2,%3}, [%4];"
                             : "=r"(bb[1][0]), "=r"(bb[1][1]), "=r"(bb[1][2]), "=r"(bb[1][3])
                             : "r"(addr));
            }
#pragma unroll
            for (int n = 0; n < 4; n++) {
                asm volatile(
                    "mma.sync.aligned.m16n8k16.row.col.f32.bf16.bf16.f32 "
                    "{%0,%1,%2,%3}, {%4,%5,%6,%7}, {%8,%9}, {%0,%1,%2,%3};"
                    : "+f"(acc[n][0]), "+f"(acc[n][1]),
                      "+f"(acc[n][2]), "+f"(acc[n][3])
                    : "r"(af[0]), "r"(af[1]), "r"(af[2]), "r"(af[3]),
                      "r"(bb[n >> 1][2 * (n & 1)]), "r"(bb[n >> 1][2 * (n & 1) + 1]));
            }
        }

        asm volatile("cp.async.wait_group 0;");
    }

#pragma unroll
    for (int m = 0; m < 4; m++) {
#pragma unroll
        for (int o = 16; o; o >>= 1) lacc[m] += __shfl_xor_sync(0xffffffffu, lacc[m], o);
        if (lane == 0) l_s[w + 32 * m] = lacc[m];
    }
    __syncthreads();

#pragma unroll
    for (int rp = 0; rp < 2; rp++) {
        int rl = cc * 16 + (lane >> 2) + 8 * rp;
        float invl = 1.0f / l_s[rl];
        int i = i0 + rl;
#pragma unroll
        for (int n = 0; n < 4; n++) {
            int col = dd * 32 + n * 8 + (lane & 3) * 2;
            const float2 r = *(const float2*)(hbf + (size_t)i * F_SZ + col);
            float ox = acc[n][2 * rp]     * invl + r.x;
            float oy = acc[n][2 * rp + 1] * invl + r.y;
            ox = ox > 0.0f ? ox : __expf(ox) - 1.0f;
            oy = oy > 0.0f ? oy : __expf(oy) - 1.0f;
            *(float2*)(out + ((size_t)bN + i) * F_SZ + col) = make_float2(ox, oy);
        }
    }
}

// ---------------------------------------------------------------------------
extern "C" void kernel_launch(void* const* d_in, const int* in_sizes, int n_in,
                              void* d_out, int out_size)
{
    const float* x     = (const float*)d_in[0];
    const int*   adj   = (const int*)d_in[1];
    const float* W     = (const float*)d_in[2];
    const float* a     = (const float*)d_in[3];
    const float* nw    = (const float*)d_in[4];
    const float* nb    = (const float*)d_in[5];
    const float* gamma = (const float*)d_in[6];
    const float* beta  = (const float*)d_in[7];
    float* out = (float*)d_out;

    const int prep_smem = 27392 * 4;                           // 109568 B (x2/SM OK)
    const int attn_smem = 139264 + 512;                        // 139776 B
    cudaFuncSetAttribute(prep_kernel, cudaFuncAttributeMaxDynamicSharedMemorySize, prep_smem);
    cudaFuncSetAttribute(attn_kernel, cudaFuncAttributeMaxDynamicSharedMemorySize, attn_smem);

    prep_kernel<<<768, 256, prep_smem>>>(x, adj, W, a, nw, nb, gamma, beta);

    dim3 grid(N_SZ / 128, B_SZ);
    attn_kernel<<<grid, 1024, attn_smem>>>(out);
}

// round 17
// speedup vs baseline: 1.2816x; 1.0071x over previous
#include <cuda_runtime.h>
#include <cuda_bf16.h>
#include <math.h>

#define B_SZ 8
#define N_SZ 2048
#define F_SZ 128
#define ROWS_TOTAL (B_SZ * N_SZ)
#define ALPHA 0.2f
#define LN_EPS 1e-5f

// Scratch (__device__ globals: allocation-free rule)
__device__ float          g_h [ROWS_TOTAL * F_SZ];   // post-LN h fp32 (residual)
__device__ __nv_bfloat16  g_hb[ROWS_TOTAL * F_SZ];   // post-LN h bf16 (mma B operand)
__device__ float4         g_rc[ROWS_TOTAL];          // {exp(s1), exp(a*s1), -, -}
__device__ float2         g_e2[ROWS_TOTAL];          // {exp(s2), exp(a*s2)}
__device__ unsigned       g_adjbits[N_SZ * (N_SZ / 32)];

__device__ __forceinline__ unsigned f2tf(float f) {
    unsigned u;
    asm("cvt.rna.tf32.f32 %0, %1;" : "=r"(u) : "f"(f));
    return u;
}

// ---------------------------------------------------------------------------
// Kernel 1 (R16, unchanged): blocks [0,256): tf32 tensor-core prep;
//   blocks [256,768): pack adj -> bitmask.
// ---------------------------------------------------------------------------
__global__ void __launch_bounds__(256, 2) prep_kernel(
    const float* __restrict__ x, const int* __restrict__ adj,
    const float* __restrict__ W, const float* __restrict__ a,
    const float* __restrict__ nw, const float* __restrict__ nb,
    const float* __restrict__ gamma, const float* __restrict__ beta)
{
    const int tid = threadIdx.x;
    if (blockIdx.x >= 256) {                               // ---- pack ----
        int gid = (blockIdx.x - 256) * 256 + tid;
        const int4* src = (const int4*)adj + (size_t)gid * 8;
        int4 v[8];
#pragma unroll
        for (int u = 0; u < 8; u++) v[u] = src[u];
        unsigned bits = 0;
#pragma unroll
        for (int u = 0; u < 8; u++) {
            bits |= (v[u].x > 0 ? 1u : 0u) << (4 * u);
            bits |= (v[u].y > 0 ? 1u : 0u) << (4 * u + 1);
            bits |= (v[u].z > 0 ? 1u : 0u) << (4 * u + 2);
            bits |= (v[u].w > 0 ? 1u : 0u) << (4 * u + 3);
        }
        g_adjbits[gid] = bits;
        return;
    }

    extern __shared__ float sm[];
    unsigned* Ws  = (unsigned*)sm;            // [128][136] tf32
    unsigned* xp  = (unsigned*)(sm + 17408);  // [64][132] tf32
    float* a1s = sm + 25856;
    float* a2s = sm + 25984;
    float* gs  = sm + 26112;
    float* bs  = sm + 26240;
    float* rsum = sm + 26368;                 // [64][4]
    float* rssq = sm + 26624;
    float* sp1  = sm + 26880;
    float* sp2  = sm + 27136;                 // total 27392 floats

    const int row0 = blockIdx.x * 64;

#pragma unroll
    for (int k = 0; k < 64; k++) {
        int idx = k * 256 + tid;
        int f = idx >> 7, o = idx & 127;
        Ws[f * 136 + o] = f2tf(W[idx]);
    }
#pragma unroll
    for (int k = 0; k < 32; k++) {
        int idx = k * 256 + tid;
        int rl = idx >> 7, f = idx & 127;
        int row = row0 + rl;
        int n = row & (N_SZ - 1);
        xp[rl * 132 + f] = f2tf(x[(size_t)row * F_SZ + f] * (1.0f + nw[n]) + nb[n]);
    }
    if (tid < 128) {
        a1s[tid] = a[tid];
        a2s[tid] = a[128 + tid];
        gs[tid]  = gamma[tid];
        bs[tid]  = beta[tid];
    }
    __syncthreads();

    const int w = tid >> 5, lane = tid & 31;
    const int g = lane >> 2, t = lane & 3;
    const int ib = (w & 1) * 32;
    const int fb = (w >> 1) * 32;
    const int fi = w >> 1;

    float acc[2][4][4];
#pragma unroll
    for (int ig = 0; ig < 2; ig++)
#pragma unroll
        for (int n = 0; n < 4; n++)
#pragma unroll
            for (int r = 0; r < 4; r++) acc[ig][n][r] = 0.0f;

#pragma unroll 4
    for (int k = 0; k < 16; k++) {
        unsigned a0[2], a1r[2], a2r[2], a3r[2];
#pragma unroll
        for (int ig = 0; ig < 2; ig++) {
            const unsigned* pr = xp + (ib + ig * 16 + g) * 132 + k * 8 + t;
            a0[ig] = pr[0];
            a2r[ig] = pr[4];
            const unsigned* pr8 = pr + 8 * 132;
            a1r[ig] = pr8[0];
            a3r[ig] = pr8[4];
        }
        unsigned b0[4], b1[4];
#pragma unroll
        for (int n = 0; n < 4; n++) {
            const unsigned* hr = Ws + (k * 8 + t) * 136 + fb + n * 8 + g;
            b0[n] = hr[0];
            b1[n] = hr[4 * 136];
        }
#pragma unroll
        for (int ig = 0; ig < 2; ig++)
#pragma unroll
            for (int n = 0; n < 4; n++) {
                asm volatile(
                    "mma.sync.aligned.m16n8k8.row.col.f32.tf32.tf32.f32 "
                    "{%0,%1,%2,%3}, {%4,%5,%6,%7}, {%8,%9}, {%0,%1,%2,%3};"
                    : "+f"(acc[ig][n][0]), "+f"(acc[ig][n][1]),
                      "+f"(acc[ig][n][2]), "+f"(acc[ig][n][3])
                    : "r"(a0[ig]), "r"(a1r[ig]), "r"(a2r[ig]), "r"(a3r[ig]),
                      "r"(b0[n]), "r"(b1[n]));
            }
    }

#pragma unroll
    for (int ig = 0; ig < 2; ig++)
#pragma unroll
        for (int rp = 0; rp < 2; rp++) {
            float s = 0.0f, ss = 0.0f;
#pragma unroll
            for (int n = 0; n < 4; n++) {
                float u0 = acc[ig][n][2 * rp], u1 = acc[ig][n][2 * rp + 1];
                s += u0 + u1;
                ss += u0 * u0 + u1 * u1;
            }
            s  += __shfl_xor_sync(0xffffffffu, s, 1);
            s  += __shfl_xor_sync(0xffffffffu, s, 2);
            ss += __shfl_xor_sync(0xffffffffu, ss, 1);
            ss += __shfl_xor_sync(0xffffffffu, ss, 2);
            if (t == 0) {
                int r = ib + ig * 16 + g + 8 * rp;
                rsum[r * 4 + fi] = s;
                rssq[r * 4 + fi] = ss;
            }
        }
    __syncthreads();

#pragma unroll
    for (int ig = 0; ig < 2; ig++)
#pragma unroll
        for (int rp = 0; rp < 2; rp++) {
            int r = ib + ig * 16 + g + 8 * rp;
            float S  = rsum[r * 4] + rsum[r * 4 + 1] + rsum[r * 4 + 2] + rsum[r * 4 + 3];
            float SS = rssq[r * 4] + rssq[r * 4 + 1] + rssq[r * 4 + 2] + rssq[r * 4 + 3];
            float mu = S * 0.0078125f;
            float var = SS * 0.0078125f - mu * mu;
            float rstd = rsqrtf(var + LN_EPS);
            int row = row0 + r;
            float s1p = 0.0f, s2p = 0.0f;
#pragma unroll
            for (int n = 0; n < 4; n++) {
                int col = fb + n * 8 + t * 2;
                float h0 = (acc[ig][n][2 * rp]     - mu) * rstd * gs[col]     + bs[col];
                float h1 = (acc[ig][n][2 * rp + 1] - mu) * rstd * gs[col + 1] + bs[col + 1];
                size_t off = (size_t)row * F_SZ + col;
                *(float2*)(g_h + off) = make_float2(h0, h1);
                __nv_bfloat162 hb = __floats2bfloat162_rn(h0, h1);
                *(__nv_bfloat162*)(g_hb + off) = hb;
                s1p += h0 * a1s[col] + h1 * a1s[col + 1];
                s2p += h0 * a2s[col] + h1 * a2s[col + 1];
            }
            s1p += __shfl_xor_sync(0xffffffffu, s1p, 1);
            s1p += __shfl_xor_sync(0xffffffffu, s1p, 2);
            s2p += __shfl_xor_sync(0xffffffffu, s2p, 1);
            s2p += __shfl_xor_sync(0xffffffffu, s2p, 2);
            if (t == 0) {
                sp1[r * 4 + fi] = s1p;
                sp2[r * 4 + fi] = s2p;
            }
        }
    __syncthreads();

    if (fi == 0 && t == 0) {
#pragma unroll
        for (int ig = 0; ig < 2; ig++)
#pragma unroll
            for (int rp = 0; rp < 2; rp++) {
                int r = ib + ig * 16 + g + 8 * rp;
                float s1 = sp1[r * 4] + sp1[r * 4 + 1] + sp1[r * 4 + 2] + sp1[r * 4 + 3];
                float s2 = sp2[r * 4] + sp2[r * 4 + 1] + sp2[r * 4 + 2] + sp2[r * 4 + 3];
                int row = row0 + r;
                g_rc[row] = make_float4(__expf(s1), __expf(ALPHA * s1), 0.0f, 0.0f);
                g_e2[row] = make_float2(__expf(s2), __expf(ALPHA * s2));
            }
    }
}

// ---------------------------------------------------------------------------
// Kernel 2: attention, 64-row CTAs x 512 threads, 2 CTAs/SM (grid 32x8 = 256
// = one wave). Two independent CTAs per SM fill each other's barrier shadows.
// mma: warp w (0..15): cc=w&3 -> i-group rows cc*16, dd=w>>2 -> f-cols dd*32.
// pass-1: warp w owns rows {w, w+16, w+32, w+48}; lane owns j=4*lane..+3.
// SMEM: Hs[2][128][272B]=69632 + Ps[2][64][272B]=34816 + l_s[64] = 104704 B.
// ---------------------------------------------------------------------------
__global__ void __launch_bounds__(512, 2) attn_kernel(float* __restrict__ out)
{
    extern __shared__ char smc[];
    const unsigned HS_BYTES = 128 * 272;             // 34816
    const unsigned PS_OFF   = 2 * HS_BYTES;          // 69632
    const unsigned PS_BYTES = 64 * 272;              // 17408
    const unsigned LS_OFF   = PS_OFF + 2 * PS_BYTES; // 104448

    unsigned* Ps32 = (unsigned*)(smc + PS_OFF);
    float*    l_s  = (float*)(smc + LS_OFF);         // [64]

    const unsigned smemBase = (unsigned)__cvta_generic_to_shared(smc);
    const unsigned psBase   = smemBase + PS_OFF;

    const int tid  = threadIdx.x;
    const int w    = tid >> 5;          // 0..15
    const int lane = tid & 31;
    const int cc   = w & 3;             // mma i-group
    const int dd   = w >> 2;            // mma f-block
    const int b    = blockIdx.y;
    const int i0   = blockIdx.x * 64;
    const int bN   = b * N_SZ;

    const __nv_bfloat16* hbb = g_hb + (size_t)bN * F_SZ;
    const float*         hbf = g_h  + (size_t)bN * F_SZ;

    // ---- pass-1 identity: rows w+16m, j = 4*lane..+3 ----
    float E1[4], F1[4];
#pragma unroll
    for (int m = 0; m < 4; m++) {
        float4 rc = g_rc[bN + i0 + w + 16 * m];
        E1[m] = rc.x; F1[m] = rc.y;
    }
    const unsigned* mbase0 = g_adjbits + (size_t)(i0 + w) * 64 + (lane >> 3);
    const float2*   e2b    = g_e2 + bN + 4 * lane;     // + T*128 (+2 for 2nd float4)
    const unsigned  sh0    = 4u * (unsigned)(lane & 7);

    // ---- mma ldmatrix addresses ----
    const unsigned aOff  = psBase + (unsigned)(cc * 16 + (lane & 15)) * 272
                         + (unsigned)(lane >> 4) * 16;
    const unsigned bRow  = (unsigned)(lane & 15) * 272;
    const unsigned bCol0 = (unsigned)(dd * 32 + (lane >> 4) * 8) * 2;
    const unsigned bCol1 = bCol0 + 32;

    float acc[4][4];
#pragma unroll
    for (int n = 0; n < 4; n++)
#pragma unroll
        for (int r = 0; r < 4; r++) acc[n][r] = 0.0f;
    float lacc[4] = {0.f, 0.f, 0.f, 0.f};

    // ---- staging: tile T (128x128 bf16 = 32KB) via 4 cp.async per thread ----
    auto stage = [&](int T, int buf) {
        unsigned dbase = smemBase + (unsigned)buf * HS_BYTES;
#pragma unroll
        for (int kk = 0; kk < 4; kk++) {
            int idx = kk * 512 + tid;
            int row = idx >> 4, c16 = idx & 15;
            unsigned dst = dbase + (unsigned)row * 272 + (unsigned)c16 * 16;
            const void* src = hbb + (size_t)(T * 128 + row) * F_SZ + c16 * 8;
            asm volatile("cp.async.cg.shared.global [%0], [%1], 16;" :: "r"(dst), "l"(src));
        }
        asm volatile("cp.async.commit_group;");
    };

    // ---- pass 1 for tile T into Ps[buf]: rows w+16m ----
    auto pass1 = [&](int T, int buf) {
        unsigned mw[4];
#pragma unroll
        for (int m = 0; m < 4; m++) mw[m] = __ldg(mbase0 + m * 16 * 64 + 4 * T);
        float4 ef0 = __ldg((const float4*)(e2b + T * 128));       // j=4l, 4l+1
        float4 ef1 = __ldg((const float4*)(e2b + T * 128 + 2));   // j=4l+2, 4l+3
        unsigned* psb = Ps32 + buf * 4352 + 2 * lane;
#pragma unroll
        for (int m = 0; m < 4; m++) {
            unsigned bits = (mw[m] >> sh0) & 0xFu;
            float pa0 = fmaxf(E1[m] * ef0.x, F1[m] * ef0.y);
            float pb0 = fmaxf(E1[m] * ef0.z, F1[m] * ef0.w);
            float pa1 = fmaxf(E1[m] * ef1.x, F1[m] * ef1.y);
            float pb1 = fmaxf(E1[m] * ef1.z, F1[m] * ef1.w);
            pa0 = (bits & 1u) ? pa0 : 0.0f;
            pb0 = (bits & 2u) ? pb0 : 0.0f;
            pa1 = (bits & 4u) ? pa1 : 0.0f;
            pb1 = (bits & 8u) ? pb1 : 0.0f;
            __nv_bfloat162 q0 = __floats2bfloat162_rn(pa0, pb0);
            __nv_bfloat162 q1 = __floats2bfloat162_rn(pa1, pb1);
            uint2 qq = make_uint2(*(unsigned*)&q0, *(unsigned*)&q1);
            *(uint2*)(psb + (w + 16 * m) * 68) = qq;
            lacc[m] += (pa0 + pb0) + (pa1 + pb1);
        }
    };

    // ---- prologue: tile 0 ----
    stage(0, 0);
    pass1(0, 0);
    asm volatile("cp.async.wait_group 0;");

    for (int T = 0; T < 16; T++) {
        const int buf = T & 1;
        __syncthreads();   // Ps[buf], Hs[buf] (tile T) visible to all warps

        if (T < 15) {
            stage(T + 1, buf ^ 1);
            pass1(T + 1, buf ^ 1);
        }

        // ---- mma(T): ACC += P[cc-group] @ H[:, dd-slab] ----
        const unsigned hsB = smemBase + (unsigned)buf * HS_BYTES;
        const unsigned psB = (unsigned)buf * PS_BYTES;
#pragma unroll
        for (int k = 0; k < 8; k++) {
            unsigned af[4];
            {
                unsigned addr = aOff + psB + (unsigned)k * 32;
                asm volatile("ldmatrix.sync.aligned.m8n8.x4.shared.b16 {%0,%1,%2,%3}, [%4];"
                             : "=r"(af[0]), "=r"(af[1]), "=r"(af[2]), "=r"(af[3])
                             : "r"(addr));
            }
            unsigned bb[2][4];
            {
                unsigned addr = hsB + bRow + (unsigned)k * 16 * 272 + bCol0;
                asm volatile("ldmatrix.sync.aligned.m8n8.x4.trans.shared.b16 {%0,%1,%2,%3}, [%4];"
                             : "=r"(bb[0][0]), "=r"(bb[0][1]), "=r"(bb[0][2]), "=r"(bb[0][3])
                             : "r"(addr));
                addr = hsB + bRow + (unsigned)k * 16 * 272 + bCol1;
                asm volatile("ldmatrix.sync.aligned.m8n8.x4.trans.shared.b16 {%0,%1,%2,%3}, [%4];"
                             : "=r"(bb[1][0]), "=r"(bb[1][1]), "=r"(bb[1][2]), "=r"(bb[1][3])
                             : "r"(addr));
            }
#pragma unroll
            for (int n = 0; n < 4; n++) {
                asm volatile(
                    "mma.sync.aligned.m16n8k16.row.col.f32.bf16.bf16.f32 "
                    "{%0,%1,%2,%3}, {%4,%5,%6,%7}, {%8,%9}, {%0,%1,%2,%3};"
                    : "+f"(acc[n][0]), "+f"(acc[n][1]),
                      "+f"(acc[n][2]), "+f"(acc[n][3])
                    : "r"(af[0]), "r"(af[1]), "r"(af[2]), "r"(af[3]),
                      "r"(bb[n >> 1][2 * (n & 1)]), "r"(bb[n >> 1][2 * (n & 1) + 1]));
            }
        }

        asm volatile("cp.async.wait_group 0;");   // own stage(T+1) copies landed
    }

    // ---- l: full warp reduce (each row owned by exactly one warp) ----
#pragma unroll
    for (int m = 0; m < 4; m++) {
#pragma unroll
        for (int o = 16; o; o >>= 1) lacc[m] += __shfl_xor_sync(0xffffffffu, lacc[m], o);
        if (lane == 0) l_s[w + 16 * m] = lacc[m];
    }
    __syncthreads();

    // ---- epilogue: normalize, +residual, elu ----
#pragma unroll
    for (int rp = 0; rp < 2; rp++) {
        int rl = cc * 16 + (lane >> 2) + 8 * rp;
        float invl = 1.0f / l_s[rl];
        int i = i0 + rl;
#pragma unroll
        for (int n = 0; n < 4; n++) {
            int col = dd * 32 + n * 8 + (lane & 3) * 2;
            const float2 r = *(const float2*)(hbf + (size_t)i * F_SZ + col);
            float ox = acc[n][2 * rp]     * invl + r.x;
            float oy = acc[n][2 * rp + 1] * invl + r.y;
            ox = ox > 0.0f ? ox : __expf(ox) - 1.0f;
            oy = oy > 0.0f ? oy : __expf(oy) - 1.0f;
            *(float2*)(out + ((size_t)bN + i) * F_SZ + col) = make_float2(ox, oy);
        }
    }
}

// ---------------------------------------------------------------------------
extern "C" void kernel_launch(void* const* d_in, const int* in_sizes, int n_in,
                              void* d_out, int out_size)
{
    const float* x     = (const float*)d_in[0];
    const int*   adj   = (const int*)d_in[1];
    const float* W     = (const float*)d_in[2];
    const float* a     = (const float*)d_in[3];
    const float* nw    = (const float*)d_in[4];
    const float* nb    = (const float*)d_in[5];
    const float* gamma = (const float*)d_in[6];
    const float* beta  = (const float*)d_in[7];
    float* out = (float*)d_out;

    const int prep_smem = 27392 * 4;                 // 109568 B (x2/SM OK)
    const int attn_smem = 104448 + 256;              // 104704 B (x2/SM = 209408 OK)
    cudaFuncSetAttribute(prep_kernel, cudaFuncAttributeMaxDynamicSharedMemorySize, prep_smem);
    cudaFuncSetAttribute(attn_kernel, cudaFuncAttributeMaxDynamicSharedMemorySize, attn_smem);

    prep_kernel<<<768, 256, prep_smem>>>(x, adj, W, a, nw, nb, gamma, beta);

    dim3 grid(N_SZ / 64, B_SZ);
    attn_kernel<<<grid, 512, attn_smem>>>(out);
}